// round 5
// baseline (speedup 1.0000x reference)
#include <cuda_runtime.h>

#define D_IN 8
#define HID 64
#define EPS 1e-5f

typedef unsigned long long u64;

__device__ __forceinline__ u64 pack2(float lo, float hi) {
    u64 r; asm("mov.b64 %0,{%1,%2};" : "=l"(r) : "f"(lo), "f"(hi)); return r;
}
__device__ __forceinline__ void unpack2(u64 v, float& lo, float& hi) {
    asm("mov.b64 {%0,%1},%2;" : "=f"(lo), "=f"(hi) : "l"(v));
}
__device__ __forceinline__ u64 ffma2(u64 a, u64 b, u64 c) {
    u64 d; asm("fma.rn.f32x2 %0,%1,%2,%3;" : "=l"(d) : "l"(a), "l"(b), "l"(c)); return d;
}
__device__ __forceinline__ float tanh_fast(float x) {
    float y; asm("tanh.approx.f32 %0,%1;" : "=f"(y) : "f"(x)); return y;
}

// Scalar LN+tanh over h[64], then pack pairs into hp[32].
__device__ __forceinline__ void ln_tanh_pack(const float* __restrict__ h,
                                             u64* __restrict__ hp,
                                             const float* __restrict__ g,
                                             const float* __restrict__ be) {
    float s0 = 0.f, s1 = 0.f, s2 = 0.f, s3 = 0.f;
#pragma unroll
    for (int i = 0; i < HID; i += 4) {
        s0 += h[i]; s1 += h[i + 1]; s2 += h[i + 2]; s3 += h[i + 3];
    }
    float m = (s0 + s1 + s2 + s3) * (1.0f / HID);
    float v0 = 0.f, v1 = 0.f, v2 = 0.f, v3 = 0.f;
#pragma unroll
    for (int i = 0; i < HID; i += 4) {
        float d0 = h[i] - m, d1 = h[i + 1] - m, d2 = h[i + 2] - m, d3 = h[i + 3] - m;
        v0 = fmaf(d0, d0, v0); v1 = fmaf(d1, d1, v1);
        v2 = fmaf(d2, d2, v2); v3 = fmaf(d3, d3, v3);
    }
    float inv = rsqrtf((v0 + v1 + v2 + v3) * (1.0f / HID) + EPS);
#pragma unroll
    for (int q = 0; q < 32; q++) {
        float a = tanh_fast(fmaf((h[2 * q] - m) * inv, g[2 * q], be[2 * q]));
        float b = tanh_fast(fmaf((h[2 * q + 1] - m) * inv, g[2 * q + 1], be[2 * q + 1]));
        hp[q] = pack2(a, b);
    }
}

__global__ __launch_bounds__(128, 2) void edge_mlp_kernel(
    const float* __restrict__ x,
    const int* __restrict__ ei,
    const float* __restrict__ W0, const float* __restrict__ b0,
    const float* __restrict__ g0, const float* __restrict__ be0,
    const float* __restrict__ W1, const float* __restrict__ b1,
    const float* __restrict__ g1, const float* __restrict__ be1,
    const float* __restrict__ W2, const float* __restrict__ b2,
    const float* __restrict__ g2, const float* __restrict__ be2,
    const float* __restrict__ W3, const float* __restrict__ b3,
    float* __restrict__ out, int n_edges)
{
    // Transposed weights: sWt[k*IN + j] = W[j*OUT + k]
    __shared__ __align__(16) float sW0t[HID * 2 * D_IN];  // [64][16]
    __shared__ __align__(16) float sW1t[HID * HID];       // [64][64]
    __shared__ __align__(16) float sW2t[HID * HID];       // [64][64]
    __shared__ __align__(16) float sW3[HID];
    __shared__ __align__(16) float sb0[HID], sb1[HID], sb2[HID];
    __shared__ __align__(16) float sg0[HID], sbe0[HID];
    __shared__ __align__(16) float sg1[HID], sbe1[HID];
    __shared__ __align__(16) float sg2[HID], sbe2[HID];
    __shared__ float sb3;

    const int t = threadIdx.x;
    // coalesced global reads; transposed smem writes
    for (int i = t; i < 2 * D_IN * HID; i += blockDim.x) {
        int j = i / HID, k = i % HID;
        sW0t[k * (2 * D_IN) + j] = W0[i];
    }
    for (int i = t; i < HID * HID; i += blockDim.x) {
        int j = i / HID, k = i % HID;
        sW1t[k * HID + j] = W1[i];
    }
    for (int i = t; i < HID * HID; i += blockDim.x) {
        int j = i / HID, k = i % HID;
        sW2t[k * HID + j] = W2[i];
    }
    if (t < HID) {
        sW3[t] = W3[t];
        sb0[t] = b0[t]; sb1[t] = b1[t]; sb2[t] = b2[t];
        sg0[t] = g0[t]; sbe0[t] = be0[t];
        sg1[t] = g1[t]; sbe1[t] = be1[t];
        sg2[t] = g2[t]; sbe2[t] = be2[t];
    }
    if (t == 0) sb3 = b3[0];
    __syncthreads();

    const float4* __restrict__ x4 = (const float4*)x;
    const int stride = gridDim.x * blockDim.x;

    for (int e = blockIdx.x * blockDim.x + threadIdx.x; e < n_edges; e += stride) {
        const int s = ei[e];
        const int d = ei[n_edges + e];

        u64 ip[D_IN];  // 16 inputs as 8 packed pairs
        {
            float4 a0 = x4[2 * s], a1 = x4[2 * s + 1];
            float4 c0 = x4[2 * d], c1 = x4[2 * d + 1];
            ip[0] = pack2(a0.x, a0.y); ip[1] = pack2(a0.z, a0.w);
            ip[2] = pack2(a1.x, a1.y); ip[3] = pack2(a1.z, a1.w);
            ip[4] = pack2(c0.x, c0.y); ip[5] = pack2(c0.z, c0.w);
            ip[6] = pack2(c1.x, c1.y); ip[7] = pack2(c1.z, c1.w);
        }

        float h[HID];
        u64 hp[HID / 2];

        // ---- Layer 0: 16 -> 64 (lanes over j; 4 k-chains) ----
#pragma unroll
        for (int kg = 0; kg < HID; kg += 4) {
            u64 a0 = 0ull, a1 = 0ull, a2 = 0ull, a3 = 0ull;
#pragma unroll
            for (int jq = 0; jq < D_IN; jq += 2) {  // 2 pairs = 4 j per step
                ulonglong2 w0 = *(const ulonglong2*)&sW0t[(kg + 0) * 16 + 2 * jq];
                ulonglong2 w1 = *(const ulonglong2*)&sW0t[(kg + 1) * 16 + 2 * jq];
                ulonglong2 w2 = *(const ulonglong2*)&sW0t[(kg + 2) * 16 + 2 * jq];
                ulonglong2 w3 = *(const ulonglong2*)&sW0t[(kg + 3) * 16 + 2 * jq];
                a0 = ffma2(ip[jq], w0.x, a0); a0 = ffma2(ip[jq + 1], w0.y, a0);
                a1 = ffma2(ip[jq], w1.x, a1); a1 = ffma2(ip[jq + 1], w1.y, a1);
                a2 = ffma2(ip[jq], w2.x, a2); a2 = ffma2(ip[jq + 1], w2.y, a2);
                a3 = ffma2(ip[jq], w3.x, a3); a3 = ffma2(ip[jq + 1], w3.y, a3);
            }
            float lo, hi;
            unpack2(a0, lo, hi); h[kg + 0] = sb0[kg + 0] + lo + hi;
            unpack2(a1, lo, hi); h[kg + 1] = sb0[kg + 1] + lo + hi;
            unpack2(a2, lo, hi); h[kg + 2] = sb0[kg + 2] + lo + hi;
            unpack2(a3, lo, hi); h[kg + 3] = sb0[kg + 3] + lo + hi;
        }
        ln_tanh_pack(h, hp, sg0, sbe0);

        // ---- Layer 1: 64 -> 64 ----
#pragma unroll
        for (int kg = 0; kg < HID; kg += 4) {
            u64 a0 = 0ull, a1 = 0ull, a2 = 0ull, a3 = 0ull;
#pragma unroll
            for (int jq = 0; jq < HID / 2; jq += 2) {
                ulonglong2 w0 = *(const ulonglong2*)&sW1t[(kg + 0) * HID + 2 * jq];
                ulonglong2 w1 = *(const ulonglong2*)&sW1t[(kg + 1) * HID + 2 * jq];
                ulonglong2 w2 = *(const ulonglong2*)&sW1t[(kg + 2) * HID + 2 * jq];
                ulonglong2 w3 = *(const ulonglong2*)&sW1t[(kg + 3) * HID + 2 * jq];
                a0 = ffma2(hp[jq], w0.x, a0); a0 = ffma2(hp[jq + 1], w0.y, a0);
                a1 = ffma2(hp[jq], w1.x, a1); a1 = ffma2(hp[jq + 1], w1.y, a1);
                a2 = ffma2(hp[jq], w2.x, a2); a2 = ffma2(hp[jq + 1], w2.y, a2);
                a3 = ffma2(hp[jq], w3.x, a3); a3 = ffma2(hp[jq + 1], w3.y, a3);
            }
            float lo, hi;
            unpack2(a0, lo, hi); h[kg + 0] = sb1[kg + 0] + lo + hi;
            unpack2(a1, lo, hi); h[kg + 1] = sb1[kg + 1] + lo + hi;
            unpack2(a2, lo, hi); h[kg + 2] = sb1[kg + 2] + lo + hi;
            unpack2(a3, lo, hi); h[kg + 3] = sb1[kg + 3] + lo + hi;
        }
        ln_tanh_pack(h, hp, sg1, sbe1);

        // ---- Layer 2: 64 -> 64 ----
#pragma unroll
        for (int kg = 0; kg < HID; kg += 4) {
            u64 a0 = 0ull, a1 = 0ull, a2 = 0ull, a3 = 0ull;
#pragma unroll
            for (int jq = 0; jq < HID / 2; jq += 2) {
                ulonglong2 w0 = *(const ulonglong2*)&sW2t[(kg + 0) * HID + 2 * jq];
                ulonglong2 w1 = *(const ulonglong2*)&sW2t[(kg + 1) * HID + 2 * jq];
                ulonglong2 w2 = *(const ulonglong2*)&sW2t[(kg + 2) * HID + 2 * jq];
                ulonglong2 w3 = *(const ulonglong2*)&sW2t[(kg + 3) * HID + 2 * jq];
                a0 = ffma2(hp[jq], w0.x, a0); a0 = ffma2(hp[jq + 1], w0.y, a0);
                a1 = ffma2(hp[jq], w1.x, a1); a1 = ffma2(hp[jq + 1], w1.y, a1);
                a2 = ffma2(hp[jq], w2.x, a2); a2 = ffma2(hp[jq + 1], w2.y, a2);
                a3 = ffma2(hp[jq], w3.x, a3); a3 = ffma2(hp[jq + 1], w3.y, a3);
            }
            float lo, hi;
            unpack2(a0, lo, hi); h[kg + 0] = sb2[kg + 0] + lo + hi;
            unpack2(a1, lo, hi); h[kg + 1] = sb2[kg + 1] + lo + hi;
            unpack2(a2, lo, hi); h[kg + 2] = sb2[kg + 2] + lo + hi;
            unpack2(a3, lo, hi); h[kg + 3] = sb2[kg + 3] + lo + hi;
        }
        ln_tanh_pack(h, hp, sg2, sbe2);

        // ---- Layer 3: 64 -> 1 (packed dot) ----
        u64 a0 = 0ull, a1 = 0ull, a2 = 0ull, a3 = 0ull;
#pragma unroll
        for (int q = 0; q < HID / 2; q += 4) {
            a0 = ffma2(hp[q],     *(const u64*)&sW3[2 * q],     a0);
            a1 = ffma2(hp[q + 1], *(const u64*)&sW3[2 * q + 2], a1);
            a2 = ffma2(hp[q + 2], *(const u64*)&sW3[2 * q + 4], a2);
            a3 = ffma2(hp[q + 3], *(const u64*)&sW3[2 * q + 6], a3);
        }
        float l0, h0, l1, h1, l2, h2, l3, h3;
        unpack2(a0, l0, h0); unpack2(a1, l1, h1);
        unpack2(a2, l2, h2); unpack2(a3, l3, h3);
        out[e] = sb3 + ((l0 + h0) + (l1 + h1)) + ((l2 + h2) + (l3 + h3));
    }
}

extern "C" void kernel_launch(void* const* d_in, const int* in_sizes, int n_in,
                              void* d_out, int out_size) {
    const float* x   = (const float*)d_in[0];
    const int*   ei  = (const int*)d_in[1];
    const float* W0 = (const float*)d_in[2];
    const float* b0 = (const float*)d_in[3];
    const float* g0 = (const float*)d_in[4];
    const float* be0 = (const float*)d_in[5];
    const float* W1 = (const float*)d_in[6];
    const float* b1 = (const float*)d_in[7];
    const float* g1 = (const float*)d_in[8];
    const float* be1 = (const float*)d_in[9];
    const float* W2 = (const float*)d_in[10];
    const float* b2 = (const float*)d_in[11];
    const float* g2 = (const float*)d_in[12];
    const float* be2 = (const float*)d_in[13];
    const float* W3 = (const float*)d_in[14];
    const float* b3 = (const float*)d_in[15];
    float* out = (float*)d_out;

    const int n_edges = in_sizes[1] / 2;

    const int threads = 128;
    const int blocks = 148 * 8;
    edge_mlp_kernel<<<blocks, threads>>>(x, ei,
                                         W0, b0, g0, be0,
                                         W1, b1, g1, be1,
                                         W2, b2, g2, be2,
                                         W3, b3, out, n_edges);
}

// round 6
// speedup vs baseline: 2.2512x; 2.2512x over previous
#include <cuda_runtime.h>

#define D_IN 8
#define HID 64
#define EPS 1e-5f

__device__ __forceinline__ float tanh_fast(float x) {
    float y; asm("tanh.approx.f32 %0,%1;" : "=f"(y) : "f"(x)); return y;
}

// LayerNorm (two-pass) + fast tanh over a 64-float register array.
__device__ __forceinline__ void ln_tanh64(float* __restrict__ h,
                                          const float* __restrict__ g,
                                          const float* __restrict__ be) {
    float s0 = 0.f, s1 = 0.f, s2 = 0.f, s3 = 0.f;
#pragma unroll
    for (int i = 0; i < HID; i += 4) {
        s0 += h[i]; s1 += h[i + 1]; s2 += h[i + 2]; s3 += h[i + 3];
    }
    float m = (s0 + s1 + s2 + s3) * (1.0f / HID);
    float v0 = 0.f, v1 = 0.f, v2 = 0.f, v3 = 0.f;
#pragma unroll
    for (int i = 0; i < HID; i += 4) {
        float d0 = h[i] - m, d1 = h[i + 1] - m;
        float d2 = h[i + 2] - m, d3 = h[i + 3] - m;
        v0 = fmaf(d0, d0, v0); v1 = fmaf(d1, d1, v1);
        v2 = fmaf(d2, d2, v2); v3 = fmaf(d3, d3, v3);
    }
    float inv = rsqrtf((v0 + v1 + v2 + v3) * (1.0f / HID) + EPS);
#pragma unroll
    for (int i = 0; i < HID; i++) {
        h[i] = tanh_fast(fmaf((h[i] - m) * inv, g[i], be[i]));
    }
}

__global__ __launch_bounds__(128) void edge_mlp_kernel(
    const float* __restrict__ x,
    const int* __restrict__ ei,
    const float* __restrict__ W0, const float* __restrict__ b0,
    const float* __restrict__ g0, const float* __restrict__ be0,
    const float* __restrict__ W1, const float* __restrict__ b1,
    const float* __restrict__ g1, const float* __restrict__ be1,
    const float* __restrict__ W2, const float* __restrict__ b2,
    const float* __restrict__ g2, const float* __restrict__ be2,
    const float* __restrict__ W3, const float* __restrict__ b3,
    float* __restrict__ out, int n_edges)
{
    __shared__ __align__(16) float sW0[2 * D_IN * HID];   // 16x64
    __shared__ __align__(16) float sW1[HID * HID];        // 64x64
    __shared__ __align__(16) float sW2[HID * HID];        // 64x64
    __shared__ __align__(16) float sW3[HID];
    __shared__ __align__(16) float sb0[HID], sb1[HID], sb2[HID];
    __shared__ __align__(16) float sg0[HID], sbe0[HID];
    __shared__ __align__(16) float sg1[HID], sbe1[HID];
    __shared__ __align__(16) float sg2[HID], sbe2[HID];
    __shared__ float sb3;

    const int t = threadIdx.x;
    for (int i = t; i < 2 * D_IN * HID; i += blockDim.x) sW0[i] = W0[i];
    for (int i = t; i < HID * HID; i += blockDim.x) sW1[i] = W1[i];
    for (int i = t; i < HID * HID; i += blockDim.x) sW2[i] = W2[i];
    if (t < HID) {
        sW3[t] = W3[t];
        sb0[t] = b0[t]; sb1[t] = b1[t]; sb2[t] = b2[t];
        sg0[t] = g0[t]; sbe0[t] = be0[t];
        sg1[t] = g1[t]; sbe1[t] = be1[t];
        sg2[t] = g2[t]; sbe2[t] = be2[t];
    }
    if (t == 0) sb3 = b3[0];
    __syncthreads();

    const float4* __restrict__ x4 = (const float4*)x;
    const int stride = gridDim.x * blockDim.x;

    for (int e = blockIdx.x * blockDim.x + threadIdx.x; e < n_edges; e += stride) {
        // Gather and concat: in[0..7] = x[start], in[8..15] = x[end]
        const int s = ei[e];
        const int d = ei[n_edges + e];
        float in[2 * D_IN];
        {
            float4 a0 = x4[2 * s], a1 = x4[2 * s + 1];
            float4 c0 = x4[2 * d], c1 = x4[2 * d + 1];
            in[0] = a0.x; in[1] = a0.y; in[2] = a0.z; in[3] = a0.w;
            in[4] = a1.x; in[5] = a1.y; in[6] = a1.z; in[7] = a1.w;
            in[8] = c0.x; in[9] = c0.y; in[10] = c0.z; in[11] = c0.w;
            in[12] = c1.x; in[13] = c1.y; in[14] = c1.z; in[15] = c1.w;
        }

        float hA[HID], hB[HID];

        // ---- Layer 0: [16] @ W0[16x64] + b0 ----
        for (int k = 0; k < HID; k += 4) {
            float4 acc = *(const float4*)&sb0[k];
#pragma unroll
            for (int j = 0; j < 2 * D_IN; j++) {
                float4 w = *(const float4*)&sW0[j * HID + k];
                acc.x = fmaf(in[j], w.x, acc.x);
                acc.y = fmaf(in[j], w.y, acc.y);
                acc.z = fmaf(in[j], w.z, acc.z);
                acc.w = fmaf(in[j], w.w, acc.w);
            }
            hA[k] = acc.x; hA[k + 1] = acc.y; hA[k + 2] = acc.z; hA[k + 3] = acc.w;
        }
        ln_tanh64(hA, sg0, sbe0);

        // ---- Layer 1: [64] @ W1[64x64] + b1 ----
        for (int k = 0; k < HID; k += 4) {
            float4 acc = *(const float4*)&sb1[k];
#pragma unroll
            for (int j = 0; j < HID; j++) {
                float4 w = *(const float4*)&sW1[j * HID + k];
                acc.x = fmaf(hA[j], w.x, acc.x);
                acc.y = fmaf(hA[j], w.y, acc.y);
                acc.z = fmaf(hA[j], w.z, acc.z);
                acc.w = fmaf(hA[j], w.w, acc.w);
            }
            hB[k] = acc.x; hB[k + 1] = acc.y; hB[k + 2] = acc.z; hB[k + 3] = acc.w;
        }
        ln_tanh64(hB, sg1, sbe1);

        // ---- Layer 2: [64] @ W2[64x64] + b2 ----
        for (int k = 0; k < HID; k += 4) {
            float4 acc = *(const float4*)&sb2[k];
#pragma unroll
            for (int j = 0; j < HID; j++) {
                float4 w = *(const float4*)&sW2[j * HID + k];
                acc.x = fmaf(hB[j], w.x, acc.x);
                acc.y = fmaf(hB[j], w.y, acc.y);
                acc.z = fmaf(hB[j], w.z, acc.z);
                acc.w = fmaf(hB[j], w.w, acc.w);
            }
            hA[k] = acc.x; hA[k + 1] = acc.y; hA[k + 2] = acc.z; hA[k + 3] = acc.w;
        }
        ln_tanh64(hA, sg2, sbe2);

        // ---- Layer 3: [64] @ W3[64x1] + b3 ----
        float o0 = sb3, o1 = 0.f, o2 = 0.f, o3 = 0.f;
#pragma unroll
        for (int j = 0; j < HID; j += 4) {
            o0 = fmaf(hA[j],     sW3[j],     o0);
            o1 = fmaf(hA[j + 1], sW3[j + 1], o1);
            o2 = fmaf(hA[j + 2], sW3[j + 2], o2);
            o3 = fmaf(hA[j + 3], sW3[j + 3], o3);
        }
        out[e] = (o0 + o1) + (o2 + o3);
    }
}

extern "C" void kernel_launch(void* const* d_in, const int* in_sizes, int n_in,
                              void* d_out, int out_size) {
    const float* x   = (const float*)d_in[0];
    const int*   ei  = (const int*)d_in[1];
    const float* W0 = (const float*)d_in[2];
    const float* b0 = (const float*)d_in[3];
    const float* g0 = (const float*)d_in[4];
    const float* be0 = (const float*)d_in[5];
    const float* W1 = (const float*)d_in[6];
    const float* b1 = (const float*)d_in[7];
    const float* g1 = (const float*)d_in[8];
    const float* be1 = (const float*)d_in[9];
    const float* W2 = (const float*)d_in[10];
    const float* b2 = (const float*)d_in[11];
    const float* g2 = (const float*)d_in[12];
    const float* be2 = (const float*)d_in[13];
    const float* W3 = (const float*)d_in[14];
    const float* b3 = (const float*)d_in[15];
    float* out = (float*)d_out;

    const int n_edges = in_sizes[1] / 2;

    const int threads = 128;
    const int blocks = 148 * 16;
    edge_mlp_kernel<<<blocks, threads>>>(x, ei,
                                         W0, b0, g0, be0,
                                         W1, b1, g1, be1,
                                         W2, b2, g2, be2,
                                         W3, b3, out, n_edges);
}

// round 7
// speedup vs baseline: 8.8248x; 3.9200x over previous
#include <cuda_runtime.h>
#include <cstdint>

#define EPS 1e-5f

__device__ __forceinline__ float tanh_fast(float x) {
    float y; asm("tanh.approx.f32 %0,%1;" : "=f"(y) : "f"(x)); return y;
}
__device__ __forceinline__ unsigned cvt_tf32(float x) {
    unsigned u; asm("cvt.rna.tf32.f32 %0,%1;" : "=r"(u) : "f"(x)); return u;
}
__device__ __forceinline__ float tf32f(float x) { return __uint_as_float(cvt_tf32(x)); }

__device__ __forceinline__ void mma8(float* d,
                                     unsigned a0, unsigned a1, unsigned a2, unsigned a3,
                                     unsigned b0, unsigned b1) {
    asm volatile(
        "mma.sync.aligned.m16n8k8.row.col.f32.tf32.tf32.f32 "
        "{%0,%1,%2,%3},{%4,%5,%6,%7},{%8,%9},{%0,%1,%2,%3};"
        : "+f"(d[0]), "+f"(d[1]), "+f"(d[2]), "+f"(d[3])
        : "r"(a0), "r"(a1), "r"(a2), "r"(a3), "r"(b0), "r"(b1));
}

// hb row stride (floats): 68 -> conflict-free A-fragment loads
#define HSTR 68

__device__ __forceinline__ void init_bias(float d[2][8][4], const float* __restrict__ sb, int tg) {
#pragma unroll
    for (int nt = 0; nt < 8; nt++) {
        float2 bb = *(const float2*)&sb[8 * nt + 2 * tg];
        d[0][nt][0] = bb.x; d[0][nt][1] = bb.y; d[0][nt][2] = bb.x; d[0][nt][3] = bb.y;
        d[1][nt][0] = bb.x; d[1][nt][1] = bb.y; d[1][nt][2] = bb.x; d[1][nt][3] = bb.y;
    }
}

template <int NKK>
__device__ __forceinline__ void mma_layer(float d[2][8][4], const float* __restrict__ bf,
                                          const float* __restrict__ hb, int g, int tg, int lane) {
#pragma unroll
    for (int kk = 0; kk < NKK; kk++) {
        unsigned A[2][4];
#pragma unroll
        for (int mt = 0; mt < 2; mt++) {
            A[mt][0] = __float_as_uint(hb[(16 * mt + g) * HSTR + 8 * kk + tg]);
            A[mt][1] = __float_as_uint(hb[(16 * mt + g + 8) * HSTR + 8 * kk + tg]);
            A[mt][2] = __float_as_uint(hb[(16 * mt + g) * HSTR + 8 * kk + tg + 4]);
            A[mt][3] = __float_as_uint(hb[(16 * mt + g + 8) * HSTR + 8 * kk + tg + 4]);
        }
#pragma unroll
        for (int nt = 0; nt < 8; nt++) {
            float2 w = *(const float2*)&bf[((kk * 8 + nt) * 32 + lane) * 2];
            unsigned b0 = __float_as_uint(w.x), b1 = __float_as_uint(w.y);
            mma8(d[0][nt], A[0][0], A[0][1], A[0][2], A[0][3], b0, b1);
            mma8(d[1][nt], A[1][0], A[1][1], A[1][2], A[1][3], b0, b1);
        }
    }
}

template <bool STORE>
__device__ __forceinline__ void ln_tanh_frag(float d[2][8][4],
                                             const float* __restrict__ sg,
                                             const float* __restrict__ sbe,
                                             float* __restrict__ hb, int g, int tg) {
#pragma unroll
    for (int mt = 0; mt < 2; mt++) {
        float s1 = 0.f, s2 = 0.f;
#pragma unroll
        for (int nt = 0; nt < 8; nt++) {
            s1 += d[mt][nt][0] + d[mt][nt][1];
            s2 += d[mt][nt][2] + d[mt][nt][3];
        }
        s1 += __shfl_xor_sync(0xffffffffu, s1, 1); s1 += __shfl_xor_sync(0xffffffffu, s1, 2);
        s2 += __shfl_xor_sync(0xffffffffu, s2, 1); s2 += __shfl_xor_sync(0xffffffffu, s2, 2);
        float m1 = s1 * (1.f / 64.f), m2 = s2 * (1.f / 64.f);
        float v1 = 0.f, v2 = 0.f;
#pragma unroll
        for (int nt = 0; nt < 8; nt++) {
            float u;
            u = d[mt][nt][0] - m1; v1 = fmaf(u, u, v1);
            u = d[mt][nt][1] - m1; v1 = fmaf(u, u, v1);
            u = d[mt][nt][2] - m2; v2 = fmaf(u, u, v2);
            u = d[mt][nt][3] - m2; v2 = fmaf(u, u, v2);
        }
        v1 += __shfl_xor_sync(0xffffffffu, v1, 1); v1 += __shfl_xor_sync(0xffffffffu, v1, 2);
        v2 += __shfl_xor_sync(0xffffffffu, v2, 1); v2 += __shfl_xor_sync(0xffffffffu, v2, 2);
        float i1 = rsqrtf(v1 * (1.f / 64.f) + EPS);
        float i2 = rsqrtf(v2 * (1.f / 64.f) + EPS);
#pragma unroll
        for (int nt = 0; nt < 8; nt++) {
            float2 gg = *(const float2*)&sg[8 * nt + 2 * tg];
            float2 bb = *(const float2*)&sbe[8 * nt + 2 * tg];
            d[mt][nt][0] = tanh_fast(fmaf((d[mt][nt][0] - m1) * i1, gg.x, bb.x));
            d[mt][nt][1] = tanh_fast(fmaf((d[mt][nt][1] - m1) * i1, gg.y, bb.y));
            d[mt][nt][2] = tanh_fast(fmaf((d[mt][nt][2] - m2) * i2, gg.x, bb.x));
            d[mt][nt][3] = tanh_fast(fmaf((d[mt][nt][3] - m2) * i2, gg.y, bb.y));
            if (STORE) {
                float2 lo = make_float2(tf32f(d[mt][nt][0]), tf32f(d[mt][nt][1]));
                float2 hi = make_float2(tf32f(d[mt][nt][2]), tf32f(d[mt][nt][3]));
                *(float2*)&hb[(16 * mt + g) * HSTR + 8 * nt + 2 * tg] = lo;
                *(float2*)&hb[(16 * mt + g + 8) * HSTR + 8 * nt + 2 * tg] = hi;
            }
        }
    }
}

// smem layout (floats):
// BF0 [1024] @ 0 | BF1 [4096] @ 1024 | BF2 [4096] @ 5120
// sb0/sb1/sb2/sg0/sbe0/sg1/sbe1/sg2/sbe2/sw3 (64 each) @ 9216..9855
// hb: 8 warps x 32 rows x HSTR @ 9856
#define SMEM_FLOATS (9856 + 8 * 32 * HSTR)

__global__ __launch_bounds__(256) void edge_mlp_tc(
    const float* __restrict__ x, const int* __restrict__ ei,
    const float* __restrict__ W0, const float* __restrict__ b0,
    const float* __restrict__ g0, const float* __restrict__ be0,
    const float* __restrict__ W1, const float* __restrict__ b1,
    const float* __restrict__ g1, const float* __restrict__ be1,
    const float* __restrict__ W2, const float* __restrict__ b2,
    const float* __restrict__ g2, const float* __restrict__ be2,
    const float* __restrict__ W3, const float* __restrict__ b3,
    float* __restrict__ out, int n_edges)
{
    extern __shared__ float sm[];
    float* BF0 = sm;
    float* BF1 = sm + 1024;
    float* BF2 = sm + 5120;
    float* sb0 = sm + 9216; float* sb1 = sm + 9280; float* sb2 = sm + 9344;
    float* sg0 = sm + 9408; float* sbe0 = sm + 9472;
    float* sg1 = sm + 9536; float* sbe1 = sm + 9600;
    float* sg2 = sm + 9664; float* sbe2 = sm + 9728;
    float* sw3 = sm + 9792;

    const int tid = threadIdx.x;

    // Stage B fragments: b0 = W[8kk+t][8nt+g], b1 = W[8kk+t+4][8nt+g]
    for (int i = tid; i < 512; i += 256) {
        int kk = i >> 8, rem = i & 255, nt = rem >> 5, ln = rem & 31;
        int gg = ln >> 2, tt = ln & 3;
        int r = 8 * kk + tt, c = 8 * nt + gg;
        BF0[2 * i]     = tf32f(W0[r * 64 + c]);
        BF0[2 * i + 1] = tf32f(W0[(r + 4) * 64 + c]);
    }
    for (int i = tid; i < 2048; i += 256) {
        int kk = i >> 8, rem = i & 255, nt = rem >> 5, ln = rem & 31;
        int gg = ln >> 2, tt = ln & 3;
        int r = 8 * kk + tt, c = 8 * nt + gg;
        BF1[2 * i]     = tf32f(W1[r * 64 + c]);
        BF1[2 * i + 1] = tf32f(W1[(r + 4) * 64 + c]);
        BF2[2 * i]     = tf32f(W2[r * 64 + c]);
        BF2[2 * i + 1] = tf32f(W2[(r + 4) * 64 + c]);
    }
    if (tid < 64) {
        sb0[tid] = b0[tid]; sb1[tid] = b1[tid]; sb2[tid] = b2[tid];
        sg0[tid] = g0[tid]; sbe0[tid] = be0[tid];
        sg1[tid] = g1[tid]; sbe1[tid] = be1[tid];
        sg2[tid] = g2[tid]; sbe2[tid] = be2[tid];
        sw3[tid] = W3[tid];
    }
    __syncthreads();
    const float b3v = b3[0];

    const int lane = tid & 31, wid = tid >> 5;
    const int g = lane >> 2, tg = lane & 3;
    float* hb = sm + 9856 + wid * (32 * HSTR);
    const float4* x4 = (const float4*)x;

    const int tile_stride = gridDim.x * 8 * 32;
    for (int base = (blockIdx.x * 8 + wid) * 32; base < n_edges; base += tile_stride) {
        // gather 32 edges -> hb[lane][0..15] (tf32-rounded)
        int e = base + lane; if (e >= n_edges) e = n_edges - 1;
        int si = ei[e], di = ei[n_edges + e];
        float4 A0 = x4[2 * si], A1 = x4[2 * si + 1];
        float4 C0 = x4[2 * di], C1 = x4[2 * di + 1];
        float* hr = &hb[lane * HSTR];
        *(float4*)&hr[0]  = make_float4(tf32f(A0.x), tf32f(A0.y), tf32f(A0.z), tf32f(A0.w));
        *(float4*)&hr[4]  = make_float4(tf32f(A1.x), tf32f(A1.y), tf32f(A1.z), tf32f(A1.w));
        *(float4*)&hr[8]  = make_float4(tf32f(C0.x), tf32f(C0.y), tf32f(C0.z), tf32f(C0.w));
        *(float4*)&hr[12] = make_float4(tf32f(C1.x), tf32f(C1.y), tf32f(C1.z), tf32f(C1.w));
        __syncwarp();

        float d[2][8][4];

        // layer 0: K=16
        init_bias(d, sb0, tg);
        mma_layer<2>(d, BF0, hb, g, tg, lane);
        __syncwarp();
        ln_tanh_frag<true>(d, sg0, sbe0, hb, g, tg);
        __syncwarp();

        // layer 1: K=64
        init_bias(d, sb1, tg);
        mma_layer<8>(d, BF1, hb, g, tg, lane);
        __syncwarp();
        ln_tanh_frag<true>(d, sg1, sbe1, hb, g, tg);
        __syncwarp();

        // layer 2: K=64 (output stays in registers)
        init_bias(d, sb2, tg);
        mma_layer<8>(d, BF2, hb, g, tg, lane);
        ln_tanh_frag<false>(d, sg2, sbe2, hb, g, tg);

        // layer 3: 64 -> 1, butterfly reduce over the 4-lane group
#pragma unroll
        for (int mt = 0; mt < 2; mt++) {
            float p1 = 0.f, p2 = 0.f;
#pragma unroll
            for (int nt = 0; nt < 8; nt++) {
                float2 w = *(const float2*)&sw3[8 * nt + 2 * tg];
                p1 = fmaf(d[mt][nt][0], w.x, p1); p1 = fmaf(d[mt][nt][1], w.y, p1);
                p2 = fmaf(d[mt][nt][2], w.x, p2); p2 = fmaf(d[mt][nt][3], w.y, p2);
            }
            p1 += __shfl_xor_sync(0xffffffffu, p1, 1); p1 += __shfl_xor_sync(0xffffffffu, p1, 2);
            p2 += __shfl_xor_sync(0xffffffffu, p2, 1); p2 += __shfl_xor_sync(0xffffffffu, p2, 2);
            if (tg == 0) {
                int e1 = base + 16 * mt + g, e2 = e1 + 8;
                if (e1 < n_edges) out[e1] = p1 + b3v;
                if (e2 < n_edges) out[e2] = p2 + b3v;
            }
        }
        __syncwarp();  // hb reads (layer-2 A frags) done before next gather overwrites
    }
}

extern "C" void kernel_launch(void* const* d_in, const int* in_sizes, int n_in,
                              void* d_out, int out_size) {
    const float* x   = (const float*)d_in[0];
    const int*   ei  = (const int*)d_in[1];
    const float* W0 = (const float*)d_in[2];
    const float* b0 = (const float*)d_in[3];
    const float* g0 = (const float*)d_in[4];
    const float* be0 = (const float*)d_in[5];
    const float* W1 = (const float*)d_in[6];
    const float* b1 = (const float*)d_in[7];
    const float* g1 = (const float*)d_in[8];
    const float* be1 = (const float*)d_in[9];
    const float* W2 = (const float*)d_in[10];
    const float* b2 = (const float*)d_in[11];
    const float* g2 = (const float*)d_in[12];
    const float* be2 = (const float*)d_in[13];
    const float* W3 = (const float*)d_in[14];
    const float* b3 = (const float*)d_in[15];
    float* out = (float*)d_out;

    const int n_edges = in_sizes[1] / 2;
    const size_t smem_bytes = SMEM_FLOATS * sizeof(float);  // ~106.5 KB

    static bool attr_set = false;
    if (!attr_set) {
        cudaFuncSetAttribute(edge_mlp_tc, cudaFuncAttributeMaxDynamicSharedMemorySize,
                             (int)smem_bytes);
        attr_set = true;
    }

    const int threads = 256;
    const int blocks = 296;  // 2 resident blocks/SM (smem-limited), grid-stride
    edge_mlp_tc<<<blocks, threads, smem_bytes>>>(x, ei,
                                                 W0, b0, g0, be0,
                                                 W1, b1, g1, be1,
                                                 W2, b2, g2, be2,
                                                 W3, b3, out, n_edges);
}